// round 8
// baseline (speedup 1.0000x reference)
#include <cuda_runtime.h>
#include <math.h>

#define NN 10000
#define NE 320000
#define SD 128
#define VD 64
#define V3 192
#define NWW 448
#define EB 8
#define THREADS 256

// ---------------- scratch (static device globals; no runtime allocation) ----
__device__ __align__(16) float g_ms[NN*SD];
__device__ __align__(16) float g_ds[NN*SD];
__device__ __align__(16) float g_mv[NN*V3];   // [n][c*3+i]
__device__ __align__(16) float g_dv[NN*V3];
__device__ __align__(16) float g_vals[NE*SD]; // [e][128]
__device__ __align__(16) float g_valv[NE*V3]; // [e][i*64+d]
__device__ float g_logit[NE*4];
__device__ float g_zz[NE*4];
__device__ unsigned int g_menc[NN*4];
__device__ float g_den[NN*4];
__device__ __align__(16) float g_outs[NN*SD];
__device__ __align__(16) float g_outv[NN*V3]; // [n][i*64+d]
// folded second-stage weights (prep kernel)
__device__ __align__(16) float g_W2s[192*128];   // [ y0*fs ; u ] -> val_s
__device__ __align__(16) float g_Wv2a[128*64];   // fs -> t  (outer with y1)
__device__ __align__(16) float g_Wv2bc[128*64];  // [y0*fv ; fv x y1] -> bcout

__device__ __forceinline__ unsigned f2ord(float f){
    unsigned u = __float_as_uint(f);
    return (u & 0x80000000u) ? ~u : (u | 0x80000000u);
}
__device__ __forceinline__ float ord2f(unsigned u){
    return (u & 0x80000000u) ? __uint_as_float(u ^ 0x80000000u)
                             : __uint_as_float(~u);
}
__device__ __forceinline__ float fast_sig(float x){
    return 1.f / (1.f + __expf(-x));
}

// ---------------- register-tiled batched GEMM -------------------------------
// X smem [ROWS][XS] (first NIN cols used), W gmem [NIN][NOUT], Y smem [ROWS][NOUT].
// Threads [TOFF, TOFF + R*C) compute TM x TN tiles.
// LANE MAPPING: row-group = t % R (adjacent lanes share cj) so that the R
// duplicate weight streams coalesce into ONE L1 request per warp. ACT1=silu.
template<int NIN, int NOUT, int ROWS, int TM, int TN, int TOFF, int ACT, int XS = NIN>
__device__ __forceinline__ void gemm_rt(const float* __restrict__ W,
                                        const float* __restrict__ bias,
                                        const float* __restrict__ X,
                                        float* __restrict__ Y)
{
    constexpr int R = ROWS / TM;
    constexpr int C = NOUT / TN;
    static_assert(R * TM == ROWS && C * TN == NOUT, "tile mismatch");
    static_assert(TOFF + R * C <= THREADS, "too many threads");
    const int t = threadIdx.x - TOFF;
    if (t >= 0 && t < R * C) {
        const int cj = (t / R) * TN;      // adjacent lanes: same cj
        const int r0 = (t % R) * TM;      // adjacent lanes: different rows
        const float* xb = X + r0 * XS;
        float* yb = Y + r0 * NOUT + cj;
        float acc[TM][TN];
        #pragma unroll
        for (int m = 0; m < TM; m++)
            #pragma unroll
            for (int n = 0; n < TN; n++)
                acc[m][n] = bias ? bias[cj + n] : 0.f;
        #pragma unroll 2
        for (int i0 = 0; i0 < NIN; i0 += 4) {
            float xr[TM][4];
            #pragma unroll
            for (int m = 0; m < TM; m++) {
                float4 x4 = *reinterpret_cast<const float4*>(xb + m * XS + i0);
                xr[m][0] = x4.x; xr[m][1] = x4.y; xr[m][2] = x4.z; xr[m][3] = x4.w;
            }
            #pragma unroll
            for (int ii = 0; ii < 4; ii++) {
                float w[TN];
                if (TN == 4) {
                    float4 w4 = *reinterpret_cast<const float4*>(W + (i0 + ii) * NOUT + cj);
                    w[0] = w4.x; w[1] = w4.y; w[2] = w4.z; w[3] = w4.w;
                } else if (TN == 2) {
                    float2 w2 = *reinterpret_cast<const float2*>(W + (i0 + ii) * NOUT + cj);
                    w[0] = w2.x; w[1] = w2.y;
                } else {
                    #pragma unroll
                    for (int n = 0; n < TN; n++) w[n] = W[(i0 + ii) * NOUT + cj + n];
                }
                #pragma unroll
                for (int m = 0; m < TM; m++)
                    #pragma unroll
                    for (int n = 0; n < TN; n++)
                        acc[m][n] = fmaf(xr[m][ii], w[n], acc[m][n]);
            }
        }
        #pragma unroll
        for (int m = 0; m < TM; m++)
            #pragma unroll
            for (int n = 0; n < TN; n++) {
                float r = acc[m][n];
                if (ACT == 1) r = r * fast_sig(r);
                yb[m * NOUT + n] = r;
            }
    }
}

// ---------------- K-1: fold tp2_w into lin2 weights -------------------------
__global__ void prep_weights(const float* __restrict__ l2Ws,
                             const float* __restrict__ l2Wv,
                             const float* __restrict__ tp2w)
{
    int i = blockIdx.x * blockDim.x + threadIdx.x;
    if (i < 192*128) {
        int r = i >> 7;
        float w = (r < 128) ? tp2w[r] : tp2w[320 + (r - 128)];
        g_W2s[i] = w * l2Ws[i];
    }
    int j = i - 192*128;
    if (j >= 0 && j < 128*64) {
        int r = j >> 6, d = j & 63;
        g_Wv2a[j] = tp2w[128 + r] * l2Wv[r*64 + d];
    }
    int k = i - 192*128 - 128*64;
    if (k >= 0 && k < 128*64) {
        int r = k >> 6, d = k & 63;
        float w = (r < 64) ? tp2w[256 + r] : tp2w[384 + (r - 64)];
        g_Wv2bc[k] = w * l2Wv[(128 + r)*64 + d];
    }
}

// ---------------- K0: init accumulators ------------------------------------
__global__ void init_kernel() {
    int i = blockIdx.x * blockDim.x + threadIdx.x;
    int stride = gridDim.x * blockDim.x;
    if (i < NN*4) { g_menc[i] = 0u; g_den[i] = 0.f; }
    for (int k = i; k < NN*SD; k += stride) g_outs[k] = 0.f;
    for (int k = i; k < NN*V3; k += stride) g_outv[k] = 0.f;
}

// ---------------- K1: node pre-linears --------------------------------------
__global__ __launch_bounds__(128) void node_pre(
    const float* __restrict__ ni,
    const float* __restrict__ Wss, const float* __restrict__ bss,
    const float* __restrict__ Wsv,
    const float* __restrict__ Wds, const float* __restrict__ Wdv)
{
    int n = blockIdx.x, tid = threadIdx.x;
    __shared__ float s[128], v[192];
    s[tid] = ni[n*320 + tid];
    for (int k = tid; k < 192; k += 128) v[k] = ni[n*320 + 128 + k];
    __syncthreads();
    float a1 = bss[tid], a2 = 0.f;
    #pragma unroll 4
    for (int i = 0; i < 128; i++) {
        float si = s[i];
        a1 = fmaf(si, Wss[i*128 + tid], a1);
        a2 = fmaf(si, Wds[i*128 + tid], a2);
    }
    g_ms[n*128 + tid] = a1;
    g_ds[n*128 + tid] = a2;
    for (int o = tid; o < 192; o += 128) {
        int i = o >> 6, d = o & 63;
        float m1 = 0.f, m2 = 0.f;
        #pragma unroll 4
        for (int c = 0; c < 64; c++) {
            float x = v[c*3 + i];
            m1 = fmaf(x, Wsv[c*64 + d], m1);
            m2 = fmaf(x, Wdv[c*64 + d], m2);
        }
        g_mv[n*192 + d*3 + i] = m1;
        g_dv[n*192 + d*3 + i] = m2;
    }
}

// ---------------- K2: fused per-edge megakernel (factored) ------------------
#define P_ES    0      /* [8][128]  -> sc (phase D out) */
#define P_EV    1024   /* [8][192]  -> bcout [24][64] (phase G out) */
#define P_WB    2560   /* [8][448]; after C: gs@2560 [8][192], gvbc@4096 [24][64], pa@5632 [8][64] */
#define P_GS    2560
#define P_GVBC  4096
#define P_PA    5632
#define P_STP   6144   /* [8][192]  TP1 s-part; reused as [y0*fs ; u] */
#define P_P     7680   /* [8][128]  p; reused as vls */
#define P_VBC   8704   /* [24][128] [q;r]; reused as [y0*fv ; fv x y1] */
#define P_WF    11776  /* [8][160] */
#define P_H0    13056  /* [8][64] */
#define P_H1    13568  /* [8][64]  -> t (phase G) */
#define P_YV    14080  /* [8][4] */
#define SMEM_FLOATS 14112

__global__ __launch_bounds__(THREADS, 3) void edge_kernel(
    const int*   __restrict__ esrc, const int* __restrict__ edst,
    const float* __restrict__ eattr, const float* __restrict__ eemb,
    const float* __restrict__ nattr,
    const float* __restrict__ rW0, const float* __restrict__ rb0,
    const float* __restrict__ rW1, const float* __restrict__ rb1,
    const float* __restrict__ rW2, const float* __restrict__ rb2,
    const float* __restrict__ attWs, const float* __restrict__ attbs,
    const float* __restrict__ l1Ws, const float* __restrict__ l1bs,
    const float* __restrict__ l1Wv,
    const float* __restrict__ l2bs, const float* __restrict__ attdot)
{
    extern __shared__ float sm[];
    __shared__ int ssrc[EB], sdst[EB];
    const int tid = threadIdx.x;
    const int e0  = blockIdx.x * EB;

    float* es   = sm + P_ES;
    float* sc   = sm + P_ES;
    float* ev   = sm + P_EV;
    float* bco  = sm + P_EV;
    float* wb   = sm + P_WB;
    float* gs   = sm + P_GS;
    float* gvbc = sm + P_GVBC;
    float* pa   = sm + P_PA;
    float* stp  = sm + P_STP;
    float* p    = sm + P_P;
    float* vls  = sm + P_P;
    float* vbc  = sm + P_VBC;
    float* wf   = sm + P_WF;
    float* h0   = sm + P_H0;
    float* h1   = sm + P_H1;
    float* tb   = sm + P_H1;
    float* yv   = sm + P_YV;

    if (tid < EB)   { ssrc[tid] = esrc[e0 + tid]; sdst[tid] = edst[e0 + tid]; }
    if (tid < EB*4) yv[tid] = eattr[e0*4 + tid];

    // A: gather es, ev; assemble wf
    for (int t = tid; t < EB*32; t += THREADS) {
        int e = t >> 5;
        float4 a = *reinterpret_cast<const float4*>(g_ms + esrc[e0+e]*SD + (t & 31)*4);
        float4 b = *reinterpret_cast<const float4*>(g_ds + edst[e0+e]*SD + (t & 31)*4);
        *reinterpret_cast<float4*>(es + t*4) = make_float4(a.x+b.x, a.y+b.y, a.z+b.z, a.w+b.w);
    }
    for (int t = tid; t < EB*48; t += THREADS) {
        int e = t / 48, q = t - e*48;
        float4 a = *reinterpret_cast<const float4*>(g_mv + esrc[e0+e]*V3 + q*4);
        float4 b = *reinterpret_cast<const float4*>(g_dv + edst[e0+e]*V3 + q*4);
        *reinterpret_cast<float4*>(ev + t*4) = make_float4(a.x+b.x, a.y+b.y, a.z+b.z, a.w+b.w);
    }
    for (int t = tid; t < EB*40; t += THREADS) {
        int e = t / 40, q = t - e*40;
        float4 val;
        if (q < 8)       val = *reinterpret_cast<const float4*>(eemb + (e0+e)*32 + q*4);
        else if (q < 24) val = *reinterpret_cast<const float4*>(nattr + esrc[e0+e]*64 + (q-8)*4);
        else             val = *reinterpret_cast<const float4*>(nattr + edst[e0+e]*64 + (q-24)*4);
        *reinterpret_cast<float4*>(wf + e*160 + q*4) = val;
    }
    __syncthreads();

    // B: radial MLP 160 -> 64 -> 64 -> 448
    gemm_rt<160, 64, EB, 2, 2, 0, 1>(rW0, rb0, wf, h0);
    __syncthreads();
    gemm_rt< 64, 64, EB, 2, 2, 0, 1>(rW1, rb1, h0, h1);
    __syncthreads();
    gemm_rt< 64,448, EB, 4, 4, 0, 0>(rW2, rb2, h1, wb);
    __syncthreads();

    // C: factored DTP1 -> stp [8][192], p [8][128], vbc [24][128]
    for (int t = tid; t < EB*128; t += THREADS) {
        int e = t >> 7, c = t & 127;
        float ee = es[t];
        stp[e*192 + c] = wb[e*448 + c] * ee * yv[e*4];
        p[t] = wb[e*448 + 128 + c] * ee;
    }
    for (int t = tid; t < EB*64; t += THREADS) {
        int e = t >> 6, cc = t & 63;
        const float* y = yv + e*4;
        const float* vv = ev + e*192 + cc*3;
        float vx = vv[0], vy = vv[1], vz = vv[2];
        stp[e*192 + 128 + cc] = wb[e*448 + 320 + cc] * (vx*y[1] + vy*y[2] + vz*y[3]);
        float qw = wb[e*448 + 256 + cc] * y[0];
        float rw = wb[e*448 + 384 + cc];
        int b = e*384;
        vbc[b +        cc] = qw*vx;
        vbc[b +  64 +  cc] = rw*(vy*y[3] - vz*y[2]);
        vbc[b + 128 +  cc] = qw*vy;
        vbc[b + 192 +  cc] = rw*(vz*y[1] - vx*y[3]);
        vbc[b + 256 +  cc] = qw*vz;
        vbc[b + 320 +  cc] = rw*(vx*y[2] - vy*y[1]);
    }
    __syncthreads();

    // D: concurrent GEMMs on disjoint thread ranges
    gemm_rt<192, 128, EB,   4, 4,   0, 0>(attWs, attbs, stp, sc);                   // thr 0-63
    gemm_rt<192, 192, EB,   4, 4,  64, 0>(l1Ws,  l1bs,  stp, gs);                   // thr 64-159
    gemm_rt<128,  64, EB*3, 6, 4, 160, 0>(l1Wv + 128*64, (const float*)0, vbc, gvbc); // thr 160-223
    gemm_rt<128,  64, EB,   4, 4, 224, 0>(l1Wv, (const float*)0, p, pa);            // thr 224-255
    __syncthreads();

    // E: gates + second-stage elementwise (DTP2 factored)
    for (int t = tid; t < EB*128; t += THREADS) {
        int e = t >> 7, c = t & 127;
        float x = gs[e*192 + c];
        float f = x * fast_sig(x);
        gs[e*192 + c] = f;                 // fs (for Wv2a GEMM)
        stp[e*192 + c] = yv[e*4] * f;      // y0*fs (for W2s GEMM)
    }
    for (int t = tid; t < EB*64; t += THREADS) {
        int e = t >> 6, d = t & 63;
        const float* y = yv + e*4;
        float sg = fast_sig(gs[e*192 + 128 + d]);
        float pav = pa[e*64 + d];
        float f0 = (y[1]*pav + gvbc[(e*3+0)*64 + d]) * sg;
        float f1 = (y[2]*pav + gvbc[(e*3+1)*64 + d]) * sg;
        float f2 = (y[3]*pav + gvbc[(e*3+2)*64 + d]) * sg;
        stp[e*192 + 128 + d] = f0*y[1] + f1*y[2] + f2*y[3];   // u
        float y0 = y[0];
        int b = e*384;
        vbc[b +        d] = y0*f0;
        vbc[b +  64 +  d] = f1*y[3] - f2*y[2];
        vbc[b + 128 +  d] = y0*f1;
        vbc[b + 192 +  d] = f2*y[1] - f0*y[3];
        vbc[b + 256 +  d] = y0*f2;
        vbc[b + 320 +  d] = f0*y[2] - f1*y[1];
    }
    __syncthreads();

    // G: concurrent output GEMMs + logits
    gemm_rt<192, 128, EB,   2, 4,   0, 0>(g_W2s,  l2bs, stp, vls);                 // thr 0-127
    gemm_rt<128,  64, EB*3, 6, 4, 128, 0>(g_Wv2bc, (const float*)0, vbc, bco);     // thr 128-191
    gemm_rt<128,  64, EB,   4, 4, 192, 0, 192>(g_Wv2a, (const float*)0, gs, tb);   // thr 192-223
    if (tid >= 224 && tid < 224 + EB*4) {
        int t = tid - 224;
        int e = t >> 2, h = t & 3;
        float acc = 0.f;
        #pragma unroll 8
        for (int k = 0; k < 32; k++) {
            float x = sc[e*128 + h*32 + k];
            float sg = fast_sig(x);
            float sl = 0.6f*x + 0.4f*x*(2.f*sg - 1.f);
            acc = fmaf(sl, attdot[h*32 + k], acc);
        }
        g_logit[(e0+e)*4 + h] = acc;
        atomicMax(&g_menc[sdst[e]*4 + h], f2ord(acc));
    }
    __syncthreads();

    // H: stores (assemble val_v = y1_i * t + bc)
    for (int t = tid; t < EB*32; t += THREADS)
        *reinterpret_cast<float4*>(g_vals + e0*SD + t*4) =
            *reinterpret_cast<const float4*>(vls + t*4);
    for (int t = tid; t < EB*48; t += THREADS) {
        int e = t / 48, q = t - e*48;
        int i = q >> 4, dd = (q & 15)*4;
        float y1i = yv[e*4 + 1 + i];
        float4 t4 = *reinterpret_cast<const float4*>(tb + e*64 + dd);
        float4 b4 = *reinterpret_cast<const float4*>(bco + (e*3+i)*64 + dd);
        float4 r = make_float4(fmaf(y1i, t4.x, b4.x), fmaf(y1i, t4.y, b4.y),
                               fmaf(y1i, t4.z, b4.z), fmaf(y1i, t4.w, b4.w));
        *reinterpret_cast<float4*>(g_valv + (e0+e)*V3 + i*64 + dd) = r;
    }
}

// ---------------- K3: z = exp(logit - m), accumulate den --------------------
__global__ void softmax_z(const int* __restrict__ edst) {
    int i = blockIdx.x * blockDim.x + threadIdx.x;
    if (i >= NE*4) return;
    int e = i >> 2, h = i & 3;
    int d = edst[e];
    float m = ord2f(g_menc[d*4 + h]);
    float z = __expf(g_logit[i] - m);
    g_zz[i] = z;
    atomicAdd(&g_den[d*4 + h], z);
}

// ---------------- K4: alpha-weighted scatter --------------------------------
__global__ __launch_bounds__(192) void scatter_kernel(const int* __restrict__ edst) {
    int e = blockIdx.x;
    int tid = threadIdx.x;
    __shared__ float a[4];
    int d = edst[e];
    if (tid < 4) a[tid] = g_zz[e*4 + tid] / (g_den[d*4 + tid] + 1e-12f);
    __syncthreads();
    if (tid < 128)
        atomicAdd(&g_outs[d*128 + tid], g_vals[e*128 + tid] * a[tid >> 5]);
    atomicAdd(&g_outv[d*192 + tid], g_valv[e*192 + tid] * a[(tid & 63) >> 4]);
}

// ---------------- K5: final node linears -> d_out ---------------------------
__global__ __launch_bounds__(128) void node_post(
    const float* __restrict__ oWs, const float* __restrict__ obs,
    const float* __restrict__ oWv, float* __restrict__ out)
{
    int n = blockIdx.x, tid = threadIdx.x;
    __shared__ float os[128], ov[192];  // ov layout [i*64+c]
    os[tid] = g_outs[n*128 + tid];
    for (int k = tid; k < 192; k += 128) ov[k] = g_outv[n*192 + k];
    __syncthreads();
    float acc = obs[tid];
    #pragma unroll 4
    for (int i = 0; i < 128; i++)
        acc = fmaf(os[i], oWs[i*128 + tid], acc);
    out[n*320 + tid] = acc;
    for (int o = tid; o < 192; o += 128) {
        int i = o >> 6, d = o & 63;
        float a2 = 0.f;
        #pragma unroll 4
        for (int c = 0; c < 64; c++)
            a2 = fmaf(ov[i*64 + c], oWv[c*64 + d], a2);
        out[n*320 + 128 + d*3 + i] = a2;
    }
}

// ---------------- host launcher ---------------------------------------------
extern "C" void kernel_launch(void* const* d_in, const int* in_sizes, int n_in,
                              void* d_out, int out_size)
{
    const float* node_input = (const float*)d_in[0];
    const float* node_attr  = (const float*)d_in[1];
    const int *esrc, *edst;
    const float *eattr, *eemb;
    if (in_sizes[2] == NE) {
        esrc  = (const int*)d_in[2];
        edst  = (const int*)d_in[3];
        eattr = (const float*)d_in[4];
        eemb  = (const float*)d_in[5];
    } else {
        eattr = (const float*)d_in[2];
        eemb  = (const float*)d_in[3];
        esrc  = (const int*)d_in[4];
        edst  = (const int*)d_in[5];
    }
    const float* Wss   = (const float*)d_in[6];
    const float* bss   = (const float*)d_in[7];
    const float* Wsv   = (const float*)d_in[8];
    const float* Wds   = (const float*)d_in[9];
    const float* Wdv   = (const float*)d_in[10];
    const float* rW0   = (const float*)d_in[11];
    const float* rb0   = (const float*)d_in[12];
    const float* rW1   = (const float*)d_in[13];
    const float* rb1   = (const float*)d_in[14];
    const float* rW2   = (const float*)d_in[15];
    const float* rb2   = (const float*)d_in[16];
    const float* l1Ws  = (const float*)d_in[17];
    const float* l1bs  = (const float*)d_in[18];
    const float* l1Wv  = (const float*)d_in[19];
    const float* attWs = (const float*)d_in[20];
    const float* attbs = (const float*)d_in[21];
    const float* tp2w  = (const float*)d_in[22];
    const float* l2Ws  = (const float*)d_in[23];
    const float* l2bs  = (const float*)d_in[24];
    const float* l2Wv  = (const float*)d_in[25];
    const float* attdot= (const float*)d_in[26];
    const float* oWs   = (const float*)d_in[27];
    const float* obs   = (const float*)d_in[28];
    const float* oWv   = (const float*)d_in[29];

    static bool attr_set = false;
    if (!attr_set) {
        cudaFuncSetAttribute(edge_kernel,
                             cudaFuncAttributeMaxDynamicSharedMemorySize,
                             SMEM_FLOATS * 4);
        attr_set = true;
    }

    prep_weights<<<(192*128 + 2*128*64 + 255)/256, 256>>>(l2Ws, l2Wv, tp2w);
    init_kernel<<<(NN*V3 + 255)/256, 256>>>();
    node_pre<<<NN, 128>>>(node_input, Wss, bss, Wsv, Wds, Wdv);
    edge_kernel<<<NE/EB, THREADS, SMEM_FLOATS*4>>>(esrc, edst, eattr, eemb, node_attr,
                                      rW0, rb0, rW1, rb1, rW2, rb2,
                                      attWs, attbs, l1Ws, l1bs, l1Wv,
                                      l2bs, attdot);
    softmax_z<<<(NE*4 + 255)/256, 256>>>(edst);
    scatter_kernel<<<NE, 192>>>(edst);
    node_post<<<NN, 128>>>(oWs, obs, oWv, (float*)d_out);
}

// round 9
// speedup vs baseline: 1.6352x; 1.6352x over previous
#include <cuda_runtime.h>
#include <math.h>

#define NN 10000
#define NE 320000
#define SD 128
#define VD 64
#define V3 192
#define NWW 448
#define EB 10
#define THREADS 288

// ---------------- scratch (static device globals; no runtime allocation) ----
__device__ __align__(16) float g_ms[NN*SD];
__device__ __align__(16) float g_ds[NN*SD];
__device__ __align__(16) float g_mv[NN*V3];   // [n][c*3+i]
__device__ __align__(16) float g_dv[NN*V3];
__device__ __align__(16) float g_vals[NE*SD]; // [e][128]
__device__ __align__(16) float g_valv[NE*V3]; // [e][i*64+d]
__device__ float g_logit[NE*4];
__device__ float g_zz[NE*4];
__device__ unsigned int g_menc[NN*4];
__device__ float g_den[NN*4];
__device__ __align__(16) float g_outs[NN*SD];
__device__ __align__(16) float g_outv[NN*V3]; // [n][i*64+d]
// folded second-stage weights (prep kernel)
__device__ __align__(16) float g_W2s[192*128];   // [ y0*fs ; u ] -> val_s
__device__ __align__(16) float g_Wv2a[128*64];   // fs -> t  (outer with y1)
__device__ __align__(16) float g_Wv2bc[128*64];  // [y0*fv ; fv x y1] -> bcout

__device__ __forceinline__ unsigned f2ord(float f){
    unsigned u = __float_as_uint(f);
    return (u & 0x80000000u) ? ~u : (u | 0x80000000u);
}
__device__ __forceinline__ float ord2f(unsigned u){
    return (u & 0x80000000u) ? __uint_as_float(u ^ 0x80000000u)
                             : __uint_as_float(~u);
}
__device__ __forceinline__ float fast_sig(float x){
    return 1.f / (1.f + __expf(-x));
}

// ---------------- register-tiled batched GEMM (R6 proven mapping) -----------
// X smem [ROWS][XS] (first NIN cols used), W gmem [NIN][NOUT], Y smem [ROWS][NOUT].
// Threads [TOFF, TOFF + R*C): cj = (t%C)*TN (adjacent lanes -> coalesced or
// naturally deduped weight loads), r0 = (t/C)*TM (broadcast X loads). ACT1=silu.
template<int NIN, int NOUT, int ROWS, int TM, int TN, int TOFF, int ACT, int XS = NIN>
__device__ __forceinline__ void gemm_rt(const float* __restrict__ W,
                                        const float* __restrict__ bias,
                                        const float* __restrict__ X,
                                        float* __restrict__ Y)
{
    constexpr int R = ROWS / TM;
    constexpr int C = NOUT / TN;
    static_assert(R * TM == ROWS && C * TN == NOUT, "tile mismatch");
    static_assert(TOFF + R * C <= THREADS, "too many threads");
    const int t = threadIdx.x - TOFF;
    if (t >= 0 && t < R * C) {
        const int cj = (t % C) * TN;
        const int r0 = (t / C) * TM;
        const float* xb = X + r0 * XS;
        float* yb = Y + r0 * NOUT + cj;
        float acc[TM][TN];
        #pragma unroll
        for (int m = 0; m < TM; m++)
            #pragma unroll
            for (int n = 0; n < TN; n++)
                acc[m][n] = bias ? bias[cj + n] : 0.f;
        #pragma unroll 2
        for (int i0 = 0; i0 < NIN; i0 += 4) {
            float xr[TM][4];
            #pragma unroll
            for (int m = 0; m < TM; m++) {
                float4 x4 = *reinterpret_cast<const float4*>(xb + m * XS + i0);
                xr[m][0] = x4.x; xr[m][1] = x4.y; xr[m][2] = x4.z; xr[m][3] = x4.w;
            }
            #pragma unroll
            for (int ii = 0; ii < 4; ii++) {
                float w[TN];
                if (TN == 4) {
                    float4 w4 = *reinterpret_cast<const float4*>(W + (i0 + ii) * NOUT + cj);
                    w[0] = w4.x; w[1] = w4.y; w[2] = w4.z; w[3] = w4.w;
                } else if (TN == 2) {
                    float2 w2 = *reinterpret_cast<const float2*>(W + (i0 + ii) * NOUT + cj);
                    w[0] = w2.x; w[1] = w2.y;
                } else {
                    #pragma unroll
                    for (int n = 0; n < TN; n++) w[n] = W[(i0 + ii) * NOUT + cj + n];
                }
                #pragma unroll
                for (int m = 0; m < TM; m++)
                    #pragma unroll
                    for (int n = 0; n < TN; n++)
                        acc[m][n] = fmaf(xr[m][ii], w[n], acc[m][n]);
            }
        }
        #pragma unroll
        for (int m = 0; m < TM; m++)
            #pragma unroll
            for (int n = 0; n < TN; n++) {
                float r = acc[m][n];
                if (ACT == 1) r = r * fast_sig(r);
                yb[m * NOUT + n] = r;
            }
    }
}

// ---------------- K-1: fold tp2_w into lin2 weights -------------------------
__global__ void prep_weights(const float* __restrict__ l2Ws,
                             const float* __restrict__ l2Wv,
                             const float* __restrict__ tp2w)
{
    int i = blockIdx.x * blockDim.x + threadIdx.x;
    if (i < 192*128) {
        int r = i >> 7;
        float w = (r < 128) ? tp2w[r] : tp2w[320 + (r - 128)];
        g_W2s[i] = w * l2Ws[i];
    }
    int j = i - 192*128;
    if (j >= 0 && j < 128*64) {
        int r = j >> 6, d = j & 63;
        g_Wv2a[j] = tp2w[128 + r] * l2Wv[r*64 + d];
    }
    int k = i - 192*128 - 128*64;
    if (k >= 0 && k < 128*64) {
        int r = k >> 6, d = k & 63;
        float w = (r < 64) ? tp2w[256 + r] : tp2w[384 + (r - 64)];
        g_Wv2bc[k] = w * l2Wv[(128 + r)*64 + d];
    }
}

// ---------------- K0: init accumulators ------------------------------------
__global__ void init_kernel() {
    int i = blockIdx.x * blockDim.x + threadIdx.x;
    int stride = gridDim.x * blockDim.x;
    if (i < NN*4) { g_menc[i] = 0u; g_den[i] = 0.f; }
    for (int k = i; k < NN*SD; k += stride) g_outs[k] = 0.f;
    for (int k = i; k < NN*V3; k += stride) g_outv[k] = 0.f;
}

// ---------------- K1: node pre-linears --------------------------------------
__global__ __launch_bounds__(128) void node_pre(
    const float* __restrict__ ni,
    const float* __restrict__ Wss, const float* __restrict__ bss,
    const float* __restrict__ Wsv,
    const float* __restrict__ Wds, const float* __restrict__ Wdv)
{
    int n = blockIdx.x, tid = threadIdx.x;
    __shared__ float s[128], v[192];
    s[tid] = ni[n*320 + tid];
    for (int k = tid; k < 192; k += 128) v[k] = ni[n*320 + 128 + k];
    __syncthreads();
    float a1 = bss[tid], a2 = 0.f;
    #pragma unroll 4
    for (int i = 0; i < 128; i++) {
        float si = s[i];
        a1 = fmaf(si, Wss[i*128 + tid], a1);
        a2 = fmaf(si, Wds[i*128 + tid], a2);
    }
    g_ms[n*128 + tid] = a1;
    g_ds[n*128 + tid] = a2;
    for (int o = tid; o < 192; o += 128) {
        int i = o >> 6, d = o & 63;
        float m1 = 0.f, m2 = 0.f;
        #pragma unroll 4
        for (int c = 0; c < 64; c++) {
            float x = v[c*3 + i];
            m1 = fmaf(x, Wsv[c*64 + d], m1);
            m2 = fmaf(x, Wdv[c*64 + d], m2);
        }
        g_mv[n*192 + d*3 + i] = m1;
        g_dv[n*192 + d*3 + i] = m2;
    }
}

// ---------------- K2: fused per-edge megakernel (factored, EB = 10) ---------
#define P_ES    0      /* [10][128] 1280 -> sc (phase D out) */
#define P_EV    1280   /* [10][192] 1920 -> bcout [30][64] (phase G out) */
#define P_WB    3200   /* [10][448] 4480; after C: gs@3200 [10][192],
                          gvbc@5120 [30][64], pa@7040 [10][64] */
#define P_GS    3200
#define P_GVBC  5120
#define P_PA    7040
#define P_STP   7680   /* [10][192] 1920  TP1 s-part; reused as [y0*fs ; u] */
#define P_P     9600   /* [10][128] 1280  p; reused as vls */
#define P_VBC   10880  /* [30][128] 3840  [q;r]; reused as [y0*fv ; fv x y1] */
#define P_WF    14720  /* [10][160] 1600 */
#define P_H0    16320  /* [10][64]  640 */
#define P_H1    16960  /* [10][64]  640  -> t (phase G) */
#define P_YV    17600  /* [10][4]   40 */
#define SMEM_FLOATS 17640

__global__ __launch_bounds__(THREADS, 3) void edge_kernel(
    const int*   __restrict__ esrc, const int* __restrict__ edst,
    const float* __restrict__ eattr, const float* __restrict__ eemb,
    const float* __restrict__ nattr,
    const float* __restrict__ rW0, const float* __restrict__ rb0,
    const float* __restrict__ rW1, const float* __restrict__ rb1,
    const float* __restrict__ rW2, const float* __restrict__ rb2,
    const float* __restrict__ attWs, const float* __restrict__ attbs,
    const float* __restrict__ l1Ws, const float* __restrict__ l1bs,
    const float* __restrict__ l1Wv,
    const float* __restrict__ l2bs, const float* __restrict__ attdot)
{
    extern __shared__ float sm[];
    __shared__ int ssrc[EB], sdst[EB];
    const int tid = threadIdx.x;
    const int e0  = blockIdx.x * EB;

    float* es   = sm + P_ES;
    float* sc   = sm + P_ES;
    float* ev   = sm + P_EV;
    float* bco  = sm + P_EV;
    float* wb   = sm + P_WB;
    float* gs   = sm + P_GS;
    float* gvbc = sm + P_GVBC;
    float* pa   = sm + P_PA;
    float* stp  = sm + P_STP;
    float* p    = sm + P_P;
    float* vls  = sm + P_P;
    float* vbc  = sm + P_VBC;
    float* wf   = sm + P_WF;
    float* h0   = sm + P_H0;
    float* h1   = sm + P_H1;
    float* tb   = sm + P_H1;
    float* yv   = sm + P_YV;

    if (tid < EB)   { ssrc[tid] = esrc[e0 + tid]; sdst[tid] = edst[e0 + tid]; }
    if (tid < EB*4) yv[tid] = eattr[e0*4 + tid];

    // A: gather es, ev; assemble wf
    for (int t = tid; t < EB*32; t += THREADS) {
        int e = t >> 5;
        float4 a = *reinterpret_cast<const float4*>(g_ms + esrc[e0+e]*SD + (t & 31)*4);
        float4 b = *reinterpret_cast<const float4*>(g_ds + edst[e0+e]*SD + (t & 31)*4);
        *reinterpret_cast<float4*>(es + t*4) = make_float4(a.x+b.x, a.y+b.y, a.z+b.z, a.w+b.w);
    }
    for (int t = tid; t < EB*48; t += THREADS) {
        int e = t / 48, q = t - e*48;
        float4 a = *reinterpret_cast<const float4*>(g_mv + esrc[e0+e]*V3 + q*4);
        float4 b = *reinterpret_cast<const float4*>(g_dv + edst[e0+e]*V3 + q*4);
        *reinterpret_cast<float4*>(ev + t*4) = make_float4(a.x+b.x, a.y+b.y, a.z+b.z, a.w+b.w);
    }
    for (int t = tid; t < EB*40; t += THREADS) {
        int e = t / 40, q = t - e*40;
        float4 val;
        if (q < 8)       val = *reinterpret_cast<const float4*>(eemb + (e0+e)*32 + q*4);
        else if (q < 24) val = *reinterpret_cast<const float4*>(nattr + esrc[e0+e]*64 + (q-8)*4);
        else             val = *reinterpret_cast<const float4*>(nattr + edst[e0+e]*64 + (q-24)*4);
        *reinterpret_cast<float4*>(wf + e*160 + q*4) = val;
    }
    __syncthreads();

    // B: radial MLP 160 -> 64 -> 64 -> 448
    gemm_rt<160, 64, EB, 5, 2, 0, 1>(rW0, rb0, wf, h0);
    __syncthreads();
    gemm_rt< 64, 64, EB, 5, 2, 0, 1>(rW1, rb1, h0, h1);
    __syncthreads();
    gemm_rt< 64,448, EB, 5, 4, 0, 0>(rW2, rb2, h1, wb);   // 224 thr
    __syncthreads();

    // C: factored DTP1 -> stp [10][192], p [10][128], vbc [30][128]
    for (int t = tid; t < EB*128; t += THREADS) {
        int e = t >> 7, c = t & 127;
        float ee = es[t];
        stp[e*192 + c] = wb[e*448 + c] * ee * yv[e*4];
        p[t] = wb[e*448 + 128 + c] * ee;
    }
    for (int t = tid; t < EB*64; t += THREADS) {
        int e = t >> 6, cc = t & 63;
        const float* y = yv + e*4;
        const float* vv = ev + e*192 + cc*3;
        float vx = vv[0], vy = vv[1], vz = vv[2];
        stp[e*192 + 128 + cc] = wb[e*448 + 320 + cc] * (vx*y[1] + vy*y[2] + vz*y[3]);
        float qw = wb[e*448 + 256 + cc] * y[0];
        float rw = wb[e*448 + 384 + cc];
        int b = e*384;
        vbc[b +        cc] = qw*vx;
        vbc[b +  64 +  cc] = rw*(vy*y[3] - vz*y[2]);
        vbc[b + 128 +  cc] = qw*vy;
        vbc[b + 192 +  cc] = rw*(vz*y[1] - vx*y[3]);
        vbc[b + 256 +  cc] = qw*vz;
        vbc[b + 320 +  cc] = rw*(vx*y[2] - vy*y[1]);
    }
    __syncthreads();

    // D: concurrent GEMMs on disjoint thread ranges (288 thr exactly)
    gemm_rt<192, 128, EB,   5, 4,   0, 0>(attWs, attbs, stp, sc);                    // thr 0-63
    gemm_rt<192, 192, EB,   5, 4,  64, 0>(l1Ws,  l1bs,  stp, gs);                    // thr 64-159
    gemm_rt<128,  64, EB*3, 5, 4, 160, 0>(l1Wv + 128*64, (const float*)0, vbc, gvbc); // thr 160-255
    gemm_rt<128,  64, EB,   5, 4, 256, 0>(l1Wv, (const float*)0, p, pa);             // thr 256-287
    __syncthreads();

    // E: gates + second-stage elementwise (DTP2 factored)
    for (int t = tid; t < EB*128; t += THREADS) {
        int e = t >> 7, c = t & 127;
        float x = gs[e*192 + c];
        float f = x * fast_sig(x);
        gs[e*192 + c] = f;                 // fs (for Wv2a GEMM)
        stp[e*192 + c] = yv[e*4] * f;      // y0*fs (for W2s GEMM)
    }
    for (int t = tid; t < EB*64; t += THREADS) {
        int e = t >> 6, d = t & 63;
        const float* y = yv + e*4;
        float sg = fast_sig(gs[e*192 + 128 + d]);
        float pav = pa[e*64 + d];
        float f0 = (y[1]*pav + gvbc[(e*3+0)*64 + d]) * sg;
        float f1 = (y[2]*pav + gvbc[(e*3+1)*64 + d]) * sg;
        float f2 = (y[3]*pav + gvbc[(e*3+2)*64 + d]) * sg;
        stp[e*192 + 128 + d] = f0*y[1] + f1*y[2] + f2*y[3];   // u
        float y0 = y[0];
        int b = e*384;
        vbc[b +        d] = y0*f0;
        vbc[b +  64 +  d] = f1*y[3] - f2*y[2];
        vbc[b + 128 +  d] = y0*f1;
        vbc[b + 192 +  d] = f2*y[1] - f0*y[3];
        vbc[b + 256 +  d] = y0*f2;
        vbc[b + 320 +  d] = f0*y[2] - f1*y[1];
    }
    __syncthreads();

    // G: concurrent output GEMMs + logits
    gemm_rt<192, 128, EB,   5, 4,   0, 0>(g_W2s,  l2bs, stp, vls);                  // thr 0-63
    gemm_rt<128,  64, EB*3, 5, 4,  64, 0>(g_Wv2bc, (const float*)0, vbc, bco);      // thr 64-159
    gemm_rt<128,  64, EB,   5, 4, 160, 0, 192>(g_Wv2a, (const float*)0, gs, tb);    // thr 160-191
    if (tid >= 192 && tid < 192 + EB*4) {
        int t = tid - 192;
        int e = t >> 2, h = t & 3;
        float acc = 0.f;
        #pragma unroll 8
        for (int k = 0; k < 32; k++) {
            float x = sc[e*128 + h*32 + k];
            float sg = fast_sig(x);
            float sl = 0.6f*x + 0.4f*x*(2.f*sg - 1.f);
            acc = fmaf(sl, attdot[h*32 + k], acc);
        }
        g_logit[(e0+e)*4 + h] = acc;
        atomicMax(&g_menc[sdst[e]*4 + h], f2ord(acc));
    }
    __syncthreads();

    // H: stores (assemble val_v = y1_i * t + bc)
    for (int t = tid; t < EB*32; t += THREADS)
        *reinterpret_cast<float4*>(g_vals + e0*SD + t*4) =
            *reinterpret_cast<const float4*>(vls + t*4);
    for (int t = tid; t < EB*48; t += THREADS) {
        int e = t / 48, q = t - e*48;
        int i = q >> 4, dd = (q & 15)*4;
        float y1i = yv[e*4 + 1 + i];
        float4 t4 = *reinterpret_cast<const float4*>(tb + e*64 + dd);
        float4 b4 = *reinterpret_cast<const float4*>(bco + (e*3+i)*64 + dd);
        float4 r = make_float4(fmaf(y1i, t4.x, b4.x), fmaf(y1i, t4.y, b4.y),
                               fmaf(y1i, t4.z, b4.z), fmaf(y1i, t4.w, b4.w));
        *reinterpret_cast<float4*>(g_valv + (e0+e)*V3 + i*64 + dd) = r;
    }
}

// ---------------- K3: z = exp(logit - m), accumulate den --------------------
__global__ void softmax_z(const int* __restrict__ edst) {
    int i = blockIdx.x * blockDim.x + threadIdx.x;
    if (i >= NE*4) return;
    int e = i >> 2, h = i & 3;
    int d = edst[e];
    float m = ord2f(g_menc[d*4 + h]);
    float z = __expf(g_logit[i] - m);
    g_zz[i] = z;
    atomicAdd(&g_den[d*4 + h], z);
}

// ---------------- K4: alpha-weighted scatter --------------------------------
__global__ __launch_bounds__(192) void scatter_kernel(const int* __restrict__ edst) {
    int e = blockIdx.x;
    int tid = threadIdx.x;
    __shared__ float a[4];
    int d = edst[e];
    if (tid < 4) a[tid] = g_zz[e*4 + tid] / (g_den[d*4 + tid] + 1e-12f);
    __syncthreads();
    if (tid < 128)
        atomicAdd(&g_outs[d*128 + tid], g_vals[e*128 + tid] * a[tid >> 5]);
    atomicAdd(&g_outv[d*192 + tid], g_valv[e*192 + tid] * a[(tid & 63) >> 4]);
}

// ---------------- K5: final node linears -> d_out ---------------------------
__global__ __launch_bounds__(128) void node_post(
    const float* __restrict__ oWs, const float* __restrict__ obs,
    const float* __restrict__ oWv, float* __restrict__ out)
{
    int n = blockIdx.x, tid = threadIdx.x;
    __shared__ float os[128], ov[192];  // ov layout [i*64+c]
    os[tid] = g_outs[n*128 + tid];
    for (int k = tid; k < 192; k += 128) ov[k] = g_outv[n*192 + k];
    __syncthreads();
    float acc = obs[tid];
    #pragma unroll 4
    for (int i = 0; i < 128; i++)
        acc = fmaf(os[i], oWs[i*128 + tid], acc);
    out[n*320 + tid] = acc;
    for (int o = tid; o < 192; o += 128) {
        int i = o >> 6, d = o & 63;
        float a2 = 0.f;
        #pragma unroll 4
        for (int c = 0; c < 64; c++)
            a2 = fmaf(ov[i*64 + c], oWv[c*64 + d], a2);
        out[n*320 + 128 + d*3 + i] = a2;
    }
}

// ---------------- host launcher ---------------------------------------------
extern "C" void kernel_launch(void* const* d_in, const int* in_sizes, int n_in,
                              void* d_out, int out_size)
{
    const float* node_input = (const float*)d_in[0];
    const float* node_attr  = (const float*)d_in[1];
    const int *esrc, *edst;
    const float *eattr, *eemb;
    if (in_sizes[2] == NE) {
        esrc  = (const int*)d_in[2];
        edst  = (const int*)d_in[3];
        eattr = (const float*)d_in[4];
        eemb  = (const float*)d_in[5];
    } else {
        eattr = (const float*)d_in[2];
        eemb  = (const float*)d_in[3];
        esrc  = (const int*)d_in[4];
        edst  = (const int*)d_in[5];
    }
    const float* Wss   = (const float*)d_in[6];
    const float* bss   = (const float*)d_in[7];
    const float* Wsv   = (const float*)d_in[8];
    const float* Wds   = (const float*)d_in[9];
    const float* Wdv   = (const float*)d_in[10];
    const float* rW0   = (const float*)d_in[11];
    const float* rb0   = (const float*)d_in[12];
    const float* rW1   = (const float*)d_in[13];
    const float* rb1   = (const float*)d_in[14];
    const float* rW2   = (const float*)d_in[15];
    const float* rb2   = (const float*)d_in[16];
    const float* l1Ws  = (const float*)d_in[17];
    const float* l1bs  = (const float*)d_in[18];
    const float* l1Wv  = (const float*)d_in[19];
    const float* attWs = (const float*)d_in[20];
    const float* attbs = (const float*)d_in[21];
    const float* tp2w  = (const float*)d_in[22];
    const float* l2Ws  = (const float*)d_in[23];
    const float* l2bs  = (const float*)d_in[24];
    const float* l2Wv  = (const float*)d_in[25];
    const float* attdot= (const float*)d_in[26];
    const float* oWs   = (const float*)d_in[27];
    const float* obs   = (const float*)d_in[28];
    const float* oWv   = (const float*)d_in[29];

    static bool attr_set = false;
    if (!attr_set) {
        cudaFuncSetAttribute(edge_kernel,
                             cudaFuncAttributeMaxDynamicSharedMemorySize,
                             SMEM_FLOATS * 4);
        attr_set = true;
    }

    prep_weights<<<(192*128 + 2*128*64 + 255)/256, 256>>>(l2Ws, l2Wv, tp2w);
    init_kernel<<<(NN*V3 + 255)/256, 256>>>();
    node_pre<<<NN, 128>>>(node_input, Wss, bss, Wsv, Wds, Wdv);
    edge_kernel<<<NE/EB, THREADS, SMEM_FLOATS*4>>>(esrc, edst, eattr, eemb, node_attr,
                                      rW0, rb0, rW1, rb1, rW2, rb2,
                                      attWs, attbs, l1Ws, l1bs, l1Wv,
                                      l2bs, attdot);
    softmax_z<<<(NE*4 + 255)/256, 256>>>(edst);
    scatter_kernel<<<NE, 192>>>(edst);
    node_post<<<NN, 128>>>(oWs, obs, oWv, (float*)d_out);
}

// round 10
// speedup vs baseline: 1.7194x; 1.0515x over previous
#include <cuda_runtime.h>
#include <math.h>

#define NN 10000
#define NE 320000
#define SD 128
#define VD 64
#define V3 192
#define NWW 448
#define EB 10
#define THREADS 288

// ---------------- scratch (static device globals; no runtime allocation) ----
__device__ __align__(16) float g_ms[NN*SD];
__device__ __align__(16) float g_ds[NN*SD];
__device__ __align__(16) float g_mv[NN*V3];   // [n][c*3+i]
__device__ __align__(16) float g_dv[NN*V3];
__device__ __align__(16) float g_vals[NE*SD]; // [e][128]
__device__ __align__(16) float g_valv[NE*V3]; // [e][i*64+d]
__device__ float g_logit[NE*4];
__device__ float g_zz[NE*4];
__device__ unsigned int g_menc[NN*4];
__device__ float g_den[NN*4];
__device__ __align__(16) float g_outs[NN*SD];
__device__ __align__(16) float g_outv[NN*V3]; // [n][i*64+d]
// folded second-stage weights (prep kernel)
__device__ __align__(16) float g_W2s[192*128];   // [ y0*fs ; u ] -> val_s
__device__ __align__(16) float g_Wv2a[128*64];   // fs -> t  (outer with y1)
__device__ __align__(16) float g_Wv2bc[128*64];  // [y0*fv ; fv x y1] -> bcout

__device__ __forceinline__ unsigned f2ord(float f){
    unsigned u = __float_as_uint(f);
    return (u & 0x80000000u) ? ~u : (u | 0x80000000u);
}
__device__ __forceinline__ float ord2f(unsigned u){
    return (u & 0x80000000u) ? __uint_as_float(u ^ 0x80000000u)
                             : __uint_as_float(~u);
}
__device__ __forceinline__ float fast_sig(float x){
    return 1.f / (1.f + __expf(-x));
}
// sm_90+ vector reduction: one L2 op per 16 bytes
__device__ __forceinline__ void red_add_v4(float* addr, float4 v){
    asm volatile("red.global.add.v4.f32 [%0], {%1, %2, %3, %4};"
                 :: "l"(addr), "f"(v.x), "f"(v.y), "f"(v.z), "f"(v.w)
                 : "memory");
}

// ---------------- register-tiled batched GEMM (R6 proven mapping) -----------
template<int NIN, int NOUT, int ROWS, int TM, int TN, int TOFF, int ACT, int XS = NIN>
__device__ __forceinline__ void gemm_rt(const float* __restrict__ W,
                                        const float* __restrict__ bias,
                                        const float* __restrict__ X,
                                        float* __restrict__ Y)
{
    constexpr int R = ROWS / TM;
    constexpr int C = NOUT / TN;
    static_assert(R * TM == ROWS && C * TN == NOUT, "tile mismatch");
    static_assert(TOFF + R * C <= THREADS, "too many threads");
    const int t = threadIdx.x - TOFF;
    if (t >= 0 && t < R * C) {
        const int cj = (t % C) * TN;
        const int r0 = (t / C) * TM;
        const float* xb = X + r0 * XS;
        float* yb = Y + r0 * NOUT + cj;
        float acc[TM][TN];
        #pragma unroll
        for (int m = 0; m < TM; m++)
            #pragma unroll
            for (int n = 0; n < TN; n++)
                acc[m][n] = bias ? bias[cj + n] : 0.f;
        #pragma unroll 2
        for (int i0 = 0; i0 < NIN; i0 += 4) {
            float xr[TM][4];
            #pragma unroll
            for (int m = 0; m < TM; m++) {
                float4 x4 = *reinterpret_cast<const float4*>(xb + m * XS + i0);
                xr[m][0] = x4.x; xr[m][1] = x4.y; xr[m][2] = x4.z; xr[m][3] = x4.w;
            }
            #pragma unroll
            for (int ii = 0; ii < 4; ii++) {
                float w[TN];
                if (TN == 4) {
                    float4 w4 = *reinterpret_cast<const float4*>(W + (i0 + ii) * NOUT + cj);
                    w[0] = w4.x; w[1] = w4.y; w[2] = w4.z; w[3] = w4.w;
                } else if (TN == 2) {
                    float2 w2 = *reinterpret_cast<const float2*>(W + (i0 + ii) * NOUT + cj);
                    w[0] = w2.x; w[1] = w2.y;
                } else {
                    #pragma unroll
                    for (int n = 0; n < TN; n++) w[n] = W[(i0 + ii) * NOUT + cj + n];
                }
                #pragma unroll
                for (int m = 0; m < TM; m++)
                    #pragma unroll
                    for (int n = 0; n < TN; n++)
                        acc[m][n] = fmaf(xr[m][ii], w[n], acc[m][n]);
            }
        }
        #pragma unroll
        for (int m = 0; m < TM; m++)
            #pragma unroll
            for (int n = 0; n < TN; n++) {
                float r = acc[m][n];
                if (ACT == 1) r = r * fast_sig(r);
                yb[m * NOUT + n] = r;
            }
    }
}

// ---------------- K-1: fold tp2_w into lin2 weights -------------------------
__global__ void prep_weights(const float* __restrict__ l2Ws,
                             const float* __restrict__ l2Wv,
                             const float* __restrict__ tp2w)
{
    int i = blockIdx.x * blockDim.x + threadIdx.x;
    if (i < 192*128) {
        int r = i >> 7;
        float w = (r < 128) ? tp2w[r] : tp2w[320 + (r - 128)];
        g_W2s[i] = w * l2Ws[i];
    }
    int j = i - 192*128;
    if (j >= 0 && j < 128*64) {
        int r = j >> 6, d = j & 63;
        g_Wv2a[j] = tp2w[128 + r] * l2Wv[r*64 + d];
    }
    int k = i - 192*128 - 128*64;
    if (k >= 0 && k < 128*64) {
        int r = k >> 6, d = k & 63;
        float w = (r < 64) ? tp2w[256 + r] : tp2w[384 + (r - 64)];
        g_Wv2bc[k] = w * l2Wv[(128 + r)*64 + d];
    }
}

// ---------------- K0: init accumulators ------------------------------------
__global__ void init_kernel() {
    int i = blockIdx.x * blockDim.x + threadIdx.x;
    int stride = gridDim.x * blockDim.x;
    if (i < NN*4) { g_menc[i] = 0u; g_den[i] = 0.f; }
    for (int k = i; k < NN*SD; k += stride) g_outs[k] = 0.f;
    for (int k = i; k < NN*V3; k += stride) g_outv[k] = 0.f;
}

// ---------------- K1: node pre-linears --------------------------------------
__global__ __launch_bounds__(128) void node_pre(
    const float* __restrict__ ni,
    const float* __restrict__ Wss, const float* __restrict__ bss,
    const float* __restrict__ Wsv,
    const float* __restrict__ Wds, const float* __restrict__ Wdv)
{
    int n = blockIdx.x, tid = threadIdx.x;
    __shared__ float s[128], v[192];
    s[tid] = ni[n*320 + tid];
    for (int k = tid; k < 192; k += 128) v[k] = ni[n*320 + 128 + k];
    __syncthreads();
    float a1 = bss[tid], a2 = 0.f;
    #pragma unroll 4
    for (int i = 0; i < 128; i++) {
        float si = s[i];
        a1 = fmaf(si, Wss[i*128 + tid], a1);
        a2 = fmaf(si, Wds[i*128 + tid], a2);
    }
    g_ms[n*128 + tid] = a1;
    g_ds[n*128 + tid] = a2;
    for (int o = tid; o < 192; o += 128) {
        int i = o >> 6, d = o & 63;
        float m1 = 0.f, m2 = 0.f;
        #pragma unroll 4
        for (int c = 0; c < 64; c++) {
            float x = v[c*3 + i];
            m1 = fmaf(x, Wsv[c*64 + d], m1);
            m2 = fmaf(x, Wdv[c*64 + d], m2);
        }
        g_mv[n*192 + d*3 + i] = m1;
        g_dv[n*192 + d*3 + i] = m2;
    }
}

// ---------------- K2: fused per-edge megakernel (factored, EB = 10) ---------
#define P_ES    0
#define P_EV    1280
#define P_WB    3200
#define P_GS    3200
#define P_GVBC  5120
#define P_PA    7040
#define P_STP   7680
#define P_P     9600
#define P_VBC   10880
#define P_WF    14720
#define P_H0    16320
#define P_H1    16960
#define P_YV    17600
#define SMEM_FLOATS 17640

__global__ __launch_bounds__(THREADS, 3) void edge_kernel(
    const int*   __restrict__ esrc, const int* __restrict__ edst,
    const float* __restrict__ eattr, const float* __restrict__ eemb,
    const float* __restrict__ nattr,
    const float* __restrict__ rW0, const float* __restrict__ rb0,
    const float* __restrict__ rW1, const float* __restrict__ rb1,
    const float* __restrict__ rW2, const float* __restrict__ rb2,
    const float* __restrict__ attWs, const float* __restrict__ attbs,
    const float* __restrict__ l1Ws, const float* __restrict__ l1bs,
    const float* __restrict__ l1Wv,
    const float* __restrict__ l2bs, const float* __restrict__ attdot)
{
    extern __shared__ float sm[];
    __shared__ int ssrc[EB], sdst[EB];
    const int tid = threadIdx.x;
    const int e0  = blockIdx.x * EB;

    float* es   = sm + P_ES;
    float* sc   = sm + P_ES;
    float* ev   = sm + P_EV;
    float* bco  = sm + P_EV;
    float* wb   = sm + P_WB;
    float* gs   = sm + P_GS;
    float* gvbc = sm + P_GVBC;
    float* pa   = sm + P_PA;
    float* stp  = sm + P_STP;
    float* p    = sm + P_P;
    float* vls  = sm + P_P;
    float* vbc  = sm + P_VBC;
    float* wf   = sm + P_WF;
    float* h0   = sm + P_H0;
    float* h1   = sm + P_H1;
    float* tb   = sm + P_H1;
    float* yv   = sm + P_YV;

    if (tid < EB)   { ssrc[tid] = esrc[e0 + tid]; sdst[tid] = edst[e0 + tid]; }
    if (tid < EB*4) yv[tid] = eattr[e0*4 + tid];

    // A: gather es, ev; assemble wf
    for (int t = tid; t < EB*32; t += THREADS) {
        int e = t >> 5;
        float4 a = *reinterpret_cast<const float4*>(g_ms + esrc[e0+e]*SD + (t & 31)*4);
        float4 b = *reinterpret_cast<const float4*>(g_ds + edst[e0+e]*SD + (t & 31)*4);
        *reinterpret_cast<float4*>(es + t*4) = make_float4(a.x+b.x, a.y+b.y, a.z+b.z, a.w+b.w);
    }
    for (int t = tid; t < EB*48; t += THREADS) {
        int e = t / 48, q = t - e*48;
        float4 a = *reinterpret_cast<const float4*>(g_mv + esrc[e0+e]*V3 + q*4);
        float4 b = *reinterpret_cast<const float4*>(g_dv + edst[e0+e]*V3 + q*4);
        *reinterpret_cast<float4*>(ev + t*4) = make_float4(a.x+b.x, a.y+b.y, a.z+b.z, a.w+b.w);
    }
    for (int t = tid; t < EB*40; t += THREADS) {
        int e = t / 40, q = t - e*40;
        float4 val;
        if (q < 8)       val = *reinterpret_cast<const float4*>(eemb + (e0+e)*32 + q*4);
        else if (q < 24) val = *reinterpret_cast<const float4*>(nattr + esrc[e0+e]*64 + (q-8)*4);
        else             val = *reinterpret_cast<const float4*>(nattr + edst[e0+e]*64 + (q-24)*4);
        *reinterpret_cast<float4*>(wf + e*160 + q*4) = val;
    }
    __syncthreads();

    // B: radial MLP 160 -> 64 -> 64 -> 448
    gemm_rt<160, 64, EB, 5, 2, 0, 1>(rW0, rb0, wf, h0);
    __syncthreads();
    gemm_rt< 64, 64, EB, 5, 2, 0, 1>(rW1, rb1, h0, h1);
    __syncthreads();
    gemm_rt< 64,448, EB, 5, 4, 0, 0>(rW2, rb2, h1, wb);
    __syncthreads();

    // C: factored DTP1 -> stp [10][192], p [10][128], vbc [30][128]
    for (int t = tid; t < EB*128; t += THREADS) {
        int e = t >> 7, c = t & 127;
        float ee = es[t];
        stp[e*192 + c] = wb[e*448 + c] * ee * yv[e*4];
        p[t] = wb[e*448 + 128 + c] * ee;
    }
    for (int t = tid; t < EB*64; t += THREADS) {
        int e = t >> 6, cc = t & 63;
        const float* y = yv + e*4;
        const float* vv = ev + e*192 + cc*3;
        float vx = vv[0], vy = vv[1], vz = vv[2];
        stp[e*192 + 128 + cc] = wb[e*448 + 320 + cc] * (vx*y[1] + vy*y[2] + vz*y[3]);
        float qw = wb[e*448 + 256 + cc] * y[0];
        float rw = wb[e*448 + 384 + cc];
        int b = e*384;
        vbc[b +        cc] = qw*vx;
        vbc[b +  64 +  cc] = rw*(vy*y[3] - vz*y[2]);
        vbc[b + 128 +  cc] = qw*vy;
        vbc[b + 192 +  cc] = rw*(vz*y[1] - vx*y[3]);
        vbc[b + 256 +  cc] = qw*vz;
        vbc[b + 320 +  cc] = rw*(vx*y[2] - vy*y[1]);
    }
    __syncthreads();

    // D: concurrent GEMMs on disjoint thread ranges (288 thr exactly)
    gemm_rt<192, 128, EB,   5, 4,   0, 0>(attWs, attbs, stp, sc);
    gemm_rt<192, 192, EB,   5, 4,  64, 0>(l1Ws,  l1bs,  stp, gs);
    gemm_rt<128,  64, EB*3, 5, 4, 160, 0>(l1Wv + 128*64, (const float*)0, vbc, gvbc);
    gemm_rt<128,  64, EB,   5, 4, 256, 0>(l1Wv, (const float*)0, p, pa);
    __syncthreads();

    // E: gates + second-stage elementwise (DTP2 factored)
    for (int t = tid; t < EB*128; t += THREADS) {
        int e = t >> 7, c = t & 127;
        float x = gs[e*192 + c];
        float f = x * fast_sig(x);
        gs[e*192 + c] = f;
        stp[e*192 + c] = yv[e*4] * f;
    }
    for (int t = tid; t < EB*64; t += THREADS) {
        int e = t >> 6, d = t & 63;
        const float* y = yv + e*4;
        float sg = fast_sig(gs[e*192 + 128 + d]);
        float pav = pa[e*64 + d];
        float f0 = (y[1]*pav + gvbc[(e*3+0)*64 + d]) * sg;
        float f1 = (y[2]*pav + gvbc[(e*3+1)*64 + d]) * sg;
        float f2 = (y[3]*pav + gvbc[(e*3+2)*64 + d]) * sg;
        stp[e*192 + 128 + d] = f0*y[1] + f1*y[2] + f2*y[3];
        float y0 = y[0];
        int b = e*384;
        vbc[b +        d] = y0*f0;
        vbc[b +  64 +  d] = f1*y[3] - f2*y[2];
        vbc[b + 128 +  d] = y0*f1;
        vbc[b + 192 +  d] = f2*y[1] - f0*y[3];
        vbc[b + 256 +  d] = y0*f2;
        vbc[b + 320 +  d] = f0*y[2] - f1*y[1];
    }
    __syncthreads();

    // G: concurrent output GEMMs + logits
    gemm_rt<192, 128, EB,   5, 4,   0, 0>(g_W2s,  l2bs, stp, vls);
    gemm_rt<128,  64, EB*3, 5, 4,  64, 0>(g_Wv2bc, (const float*)0, vbc, bco);
    gemm_rt<128,  64, EB,   5, 4, 160, 0, 192>(g_Wv2a, (const float*)0, gs, tb);
    if (tid >= 192 && tid < 192 + EB*4) {
        int t = tid - 192;
        int e = t >> 2, h = t & 3;
        float acc = 0.f;
        #pragma unroll 8
        for (int k = 0; k < 32; k++) {
            float x = sc[e*128 + h*32 + k];
            float sg = fast_sig(x);
            float sl = 0.6f*x + 0.4f*x*(2.f*sg - 1.f);
            acc = fmaf(sl, attdot[h*32 + k], acc);
        }
        g_logit[(e0+e)*4 + h] = acc;
        atomicMax(&g_menc[sdst[e]*4 + h], f2ord(acc));
    }
    __syncthreads();

    // H: stores (assemble val_v = y1_i * t + bc)
    for (int t = tid; t < EB*32; t += THREADS)
        *reinterpret_cast<float4*>(g_vals + e0*SD + t*4) =
            *reinterpret_cast<const float4*>(vls + t*4);
    for (int t = tid; t < EB*48; t += THREADS) {
        int e = t / 48, q = t - e*48;
        int i = q >> 4, dd = (q & 15)*4;
        float y1i = yv[e*4 + 1 + i];
        float4 t4 = *reinterpret_cast<const float4*>(tb + e*64 + dd);
        float4 b4 = *reinterpret_cast<const float4*>(bco + (e*3+i)*64 + dd);
        float4 r = make_float4(fmaf(y1i, t4.x, b4.x), fmaf(y1i, t4.y, b4.y),
                               fmaf(y1i, t4.z, b4.z), fmaf(y1i, t4.w, b4.w));
        *reinterpret_cast<float4*>(g_valv + (e0+e)*V3 + i*64 + dd) = r;
    }
}

// ---------------- K3: z = exp(logit - m), accumulate den --------------------
__global__ void softmax_z(const int* __restrict__ edst) {
    int i = blockIdx.x * blockDim.x + threadIdx.x;
    if (i >= NE*4) return;
    int e = i >> 2, h = i & 3;
    int d = edst[e];
    float m = ord2f(g_menc[d*4 + h]);
    float z = __expf(g_logit[i] - m);
    g_zz[i] = z;
    atomicAdd(&g_den[d*4 + h], z);
}

// ---------------- K4: alpha-weighted scatter (vector reductions) ------------
// 2 edges per block, 80 lanes/edge, red.global.add.v4.f32: 80 vec-ops/edge
// instead of 320 scalar atomics. No smem, no barrier.
__global__ __launch_bounds__(160) void scatter_kernel(const int* __restrict__ edst) {
    const int half = threadIdx.x >= 80 ? 1 : 0;
    const int t = threadIdx.x - half * 80;
    const int e = blockIdx.x * 2 + half;
    const int d = edst[e];
    if (t < 32) {
        // val_s: channels 4t..4t+3, head = (4t)>>5 = t>>3
        int h = t >> 3;
        float alpha = g_zz[e*4 + h] / (g_den[d*4 + h] + 1e-12f);
        float4 v = *reinterpret_cast<const float4*>(g_vals + e*SD + t*4);
        v.x *= alpha; v.y *= alpha; v.z *= alpha; v.w *= alpha;
        red_add_v4(g_outs + d*SD + t*4, v);
    } else {
        // val_v: k = 4q, layout [i*64 + ch], head = (k & 63) >> 4
        int q = t - 32;            // 0..47
        int k = q * 4;             // 0..188
        int h = (k & 63) >> 4;
        float alpha = g_zz[e*4 + h] / (g_den[d*4 + h] + 1e-12f);
        float4 v = *reinterpret_cast<const float4*>(g_valv + e*V3 + k);
        v.x *= alpha; v.y *= alpha; v.z *= alpha; v.w *= alpha;
        red_add_v4(g_outv + d*V3 + k, v);
    }
}

// ---------------- K5: final node linears -> d_out ---------------------------
__global__ __launch_bounds__(128) void node_post(
    const float* __restrict__ oWs, const float* __restrict__ obs,
    const float* __restrict__ oWv, float* __restrict__ out)
{
    int n = blockIdx.x, tid = threadIdx.x;
    __shared__ float os[128], ov[192];  // ov layout [i*64+c]
    os[tid] = g_outs[n*128 + tid];
    for (int k = tid; k < 192; k += 128) ov[k] = g_outv[n*192 + k];
    __syncthreads();
    float acc = obs[tid];
    #pragma unroll 4
    for (int i = 0; i < 128; i++)
        acc = fmaf(os[i], oWs[i*128 + tid], acc);
    out[n*320 + tid] = acc;
    for (int o = tid; o < 192; o += 128) {
        int i = o >> 6, d = o & 63;
        float a2 = 0.f;
        #pragma unroll 4
        for (int c = 0; c < 64; c++)
            a2 = fmaf(ov[i*64 + c], oWv[c*64 + d], a2);
        out[n*320 + 128 + d*3 + i] = a2;
    }
}

// ---------------- host launcher ---------------------------------------------
extern "C" void kernel_launch(void* const* d_in, const int* in_sizes, int n_in,
                              void* d_out, int out_size)
{
    const float* node_input = (const float*)d_in[0];
    const float* node_attr  = (const float*)d_in[1];
    const int *esrc, *edst;
    const float *eattr, *eemb;
    if (in_sizes[2] == NE) {
        esrc  = (const int*)d_in[2];
        edst  = (const int*)d_in[3];
        eattr = (const float*)d_in[4];
        eemb  = (const float*)d_in[5];
    } else {
        eattr = (const float*)d_in[2];
        eemb  = (const float*)d_in[3];
        esrc  = (const int*)d_in[4];
        edst  = (const int*)d_in[5];
    }
    const float* Wss   = (const float*)d_in[6];
    const float* bss   = (const float*)d_in[7];
    const float* Wsv   = (const float*)d_in[8];
    const float* Wds   = (const float*)d_in[9];
    const float* Wdv   = (const float*)d_in[10];
    const float* rW0   = (const float*)d_in[11];
    const float* rb0   = (const float*)d_in[12];
    const float* rW1   = (const float*)d_in[13];
    const float* rb1   = (const float*)d_in[14];
    const float* rW2   = (const float*)d_in[15];
    const float* rb2   = (const float*)d_in[16];
    const float* l1Ws  = (const float*)d_in[17];
    const float* l1bs  = (const float*)d_in[18];
    const float* l1Wv  = (const float*)d_in[19];
    const float* attWs = (const float*)d_in[20];
    const float* attbs = (const float*)d_in[21];
    const float* tp2w  = (const float*)d_in[22];
    const float* l2Ws  = (const float*)d_in[23];
    const float* l2bs  = (const float*)d_in[24];
    const float* l2Wv  = (const float*)d_in[25];
    const float* attdot= (const float*)d_in[26];
    const float* oWs   = (const float*)d_in[27];
    const float* obs   = (const float*)d_in[28];
    const float* oWv   = (const float*)d_in[29];

    static bool attr_set = false;
    if (!attr_set) {
        cudaFuncSetAttribute(edge_kernel,
                             cudaFuncAttributeMaxDynamicSharedMemorySize,
                             SMEM_FLOATS * 4);
        attr_set = true;
    }

    prep_weights<<<(192*128 + 2*128*64 + 255)/256, 256>>>(l2Ws, l2Wv, tp2w);
    init_kernel<<<(NN*V3 + 255)/256, 256>>>();
    node_pre<<<NN, 128>>>(node_input, Wss, bss, Wsv, Wds, Wdv);
    edge_kernel<<<NE/EB, THREADS, SMEM_FLOATS*4>>>(esrc, edst, eattr, eemb, node_attr,
                                      rW0, rb0, rW1, rb1, rW2, rb2,
                                      attWs, attbs, l1Ws, l1bs, l1Wv,
                                      l2bs, attdot);
    softmax_z<<<(NE*4 + 255)/256, 256>>>(edst);
    scatter_kernel<<<NE/2, 160>>>(edst);
    node_post<<<NN, 128>>>(oWs, obs, oWv, (float*)d_out);
}